// round 11
// baseline (speedup 1.0000x reference)
#include <cuda_runtime.h>
#include <math.h>
#include <stdint.h>

#define BB 4
#define CC 64
#define OO 64
#define HH 128
#define WW 128
#define HW (HH*WW)
#define KT 9
#define PX 64     // pixels per block (half row)
#define ST 68     // samp row stride (floats): 68 mod 32 == 4 -> conflict-free
#define CCB 256   // bytes per (y,x) position in x_t

// ---- smem layout (float offsets) ----
#define S_SAMP0 0                 // samp fp32 [64][68]   (4352)
#define S_SAMP1 4352              // samp fp32 [64][68]   (4352)
#define S_CWB   8704              // corner weights [2][64] float4  (512)
#define S_CIB   9216              // corner byte-offsets [2][64] int4 (512)
#define S_OFFJ  9728              // [18][64]             (1152)
#define S_OFFW  10880             // [64][20]             (1280)
#define S_SC    12160             // [18]
#define S_SB    12178             // [18]
#define S_BIAS  12196             // [64]
#define SMEM_FLOATS 12260
#define SMEM_BYTES (SMEM_FLOATS*4)

// transposed input: [B][H][W][C]
__device__ float g_xt[(size_t)BB*HH*WW*CC];
// B fragments (hi only): [k][q][nt][lane][2] = (b0_hi, b1_hi)
__device__ float g_bf[KT*8*8*32*2];

__device__ __forceinline__ float tf32r(float a) {
    uint32_t u;
    asm("cvt.rna.tf32.f32 %0, %1;" : "=r"(u) : "f"(a));
    return __uint_as_float(u);
}

// ---- transpose x [B][C][H][W] -> g_xt [B][H][W][C] ----
__global__ __launch_bounds__(256) void prep_xt_kernel(const float* __restrict__ x) {
    __shared__ float tile[64][129];
    const int blk = blockIdx.x;            // b*HH + h
    const int b = blk >> 7;
    const int h = blk & 127;
    const float* xs = x + (size_t)b*CC*HW + h*WW;
    const int tid = threadIdx.x;
    for (int idx = tid; idx < CC*WW; idx += 256) {
        int c = idx >> 7, w = idx & 127;
        tile[c][w] = xs[(size_t)c*HW + w];
    }
    __syncthreads();
    float4* ot = (float4*)(g_xt + (size_t)blk * WW * CC);
    for (int t = tid; t < WW*16; t += 256) {
        int cg = t & 15, w = t >> 4;
        ot[w*16 + cg] = make_float4(tile[4*cg][w], tile[4*cg+1][w],
                                    tile[4*cg+2][w], tile[4*cg+3][w]);
    }
}

__global__ void prep_bf_kernel(const float* __restrict__ w) {
    int i = blockIdx.x * 256 + threadIdx.x;         // over KT*8*8*32 = 18432
    if (i >= KT*8*8*32) return;
    int lane = i & 31;
    int nt   = (i >> 5) & 7;
    int q    = (i >> 8) & 7;
    int k    = i >> 11;
    int cc  = lane & 3;
    int gid = lane >> 2;
    int o   = nt*8 + gid;
    int c0  = q*8 + cc;
    int c1  = c0 + 4;
    float w0 = w[(o*CC + c0)*KT + k];
    float w1 = w[(o*CC + c1)*KT + k];
    ((float2*)g_bf)[i] = make_float2(tf32r(w0), tf32r(w1));
}

__device__ __forceinline__ void mma_tf32(float* d, const uint32_t* a, uint32_t b0, uint32_t b1) {
    asm volatile(
        "mma.sync.aligned.m16n8k8.row.col.f32.tf32.tf32.f32 "
        "{%0,%1,%2,%3}, {%4,%5,%6,%7}, {%8,%9}, {%0,%1,%2,%3};"
        : "+f"(d[0]), "+f"(d[1]), "+f"(d[2]), "+f"(d[3])
        : "r"(a[0]), "r"(a[1]), "r"(a[2]), "r"(a[3]), "r"(b0), "r"(b1));
}

__global__ __launch_bounds__(128, 4) void deform_main_kernel(
    const float* __restrict__ x,
    const float* __restrict__ off_w,
    const float* __restrict__ off_b,
    const float* __restrict__ bn_gamma,
    const float* __restrict__ bn_beta,
    const float* __restrict__ bn_mean,
    const float* __restrict__ bn_var,
    const float* __restrict__ dconv_b,
    float* __restrict__ out)
{
    extern __shared__ float smem[];

    const int tid  = threadIdx.x;
    const int lane = tid & 31;
    const int wid  = tid >> 5;          // 4 warps
    const int blk  = blockIdx.x;        // 1024 = BB*HH*2
    const int b    = blk >> 8;
    const int h    = (blk >> 1) & 127;
    const int w0   = (blk & 1) * PX;    // half-row pixel base
    const int pix  = tid & 63;          // pixel for offset branch / corner calc
    const int half = tid >> 6;
    const float* xb = x + (size_t)b * CC * HW;
    const char* xtc = (const char*)g_xt + (size_t)b * HH * WW * CCB;

    // ---- Prologue ----
    for (int i = tid; i < 18*CC; i += 128) {
        int j = i / CC, c = i % CC;
        smem[S_OFFW + c*20 + j] = off_w[i];
    }
    if (tid < 18) {
        float sc = bn_gamma[tid] * rsqrtf(bn_var[tid] + 1e-5f);
        smem[S_SC + tid] = sc;
        smem[S_SB + tid] = (off_b[tid] - bn_mean[tid]) * sc + bn_beta[tid];
    }
    if (tid >= 64 && tid < 128) smem[S_BIAS + tid - 64] = dconv_b[tid - 64];
    __syncthreads();

    // ---- Offset branch: 2 threads per pixel, 9 j's each (original layout x) ----
    {
        const int jb = half * 9;
        const int p  = h*WW + w0 + pix;
        float a9[9];
        #pragma unroll
        for (int j = 0; j < 9; j++) a9[j] = 0.f;
        #pragma unroll 4
        for (int c = 0; c < CC; c++) {
            float xv = __ldg(xb + c*HW + p);
            const float* r = smem + S_OFFW + c*20 + jb;
            #pragma unroll
            for (int j = 0; j < 9; j++) a9[j] += xv * r[j];
        }
        #pragma unroll
        for (int jj = 0; jj < 9; jj++) {
            int j = jb + jj;
            float v = a9[jj] * smem[S_SC + j] + smem[S_SB + j];
            smem[S_OFFJ + j*PX + pix] = tanhf(v) * 0.75f;
        }
    }
    __syncthreads();

    // corner calc for tap k -> smem tables buf[k&1] (threads 0..63, one pixel each)
    auto calc_corners = [&](int k) {
        if (tid < 64) {
            const int p = tid;
            const int kyi = k / 3 - 1;
            const int kxi = k % 3 - 1;
            float py = (float)(h + kyi)      + smem[S_OFFJ + (2*k)*PX + p];
            float px = (float)(w0 + p + kxi) + smem[S_OFFJ + (2*k+1)*PX + p];
            float fy = floorf(py), fx = floorf(px);
            float wy = py - fy,    wx = px - fx;
            int y0 = (int)fy, x0 = (int)fx;
            int y1 = y0 + 1,  x1 = x0 + 1;
            float vy0 = (y0 >= 0 && y0 < HH) ? 1.f : 0.f;
            float vy1 = (y1 >= 0 && y1 < HH) ? 1.f : 0.f;
            float vx0 = (x0 >= 0 && x0 < WW) ? 1.f : 0.f;
            float vx1 = (x1 >= 0 && x1 < WW) ? 1.f : 0.f;
            float4 wv;
            wv.x = (1.f - wy) * (1.f - wx) * vy0 * vx0;
            wv.y = (1.f - wy) * wx         * vy0 * vx1;
            wv.z = wy         * (1.f - wx) * vy1 * vx0;
            wv.w = wy         * wx         * vy1 * vx1;
            int yc0 = min(max(y0, 0), HH-1), yc1 = min(max(y1, 0), HH-1);
            int xc0 = min(max(x0, 0), WW-1), xc1 = min(max(x1, 0), WW-1);
            int4 iv;
            iv.x = (yc0*WW + xc0)*CCB; iv.y = (yc0*WW + xc1)*CCB;
            iv.z = (yc1*WW + xc0)*CCB; iv.w = (yc1*WW + xc1)*CCB;
            ((float4*)(smem + S_CWB))[(k & 1)*64 + p] = wv;
            ((int4*)  (smem + S_CIB))[(k & 1)*64 + p] = iv;
        }
    };

    // gather roles: warp covers pixels [16*wid, 16*wid+16); lane = (pp, cg)
    const int g_pp  = lane >> 4;        // 0/1
    const int g_cg  = lane & 15;        // channel group (4 ch)
    const int cg16  = g_cg * 16;        // byte offset within position
    const int gpix0 = 16*wid + g_pp;

    // MMA warp roles
    const int pg = wid >> 1;
    const int og = wid & 1;

    // ---- Pre-loop: corners for taps 0,1; gather tap 0 -> SAMP0 ----
    calc_corners(0);
    calc_corners(1);
    __syncthreads();
    {
        const float4* cwt = (const float4*)(smem + S_CWB);
        const int4*   cit = (const int4*)(smem + S_CIB);
        #pragma unroll
        for (int i = 0; i < 8; i++) {
            int p = gpix0 + 2*i;
            float4 cw = cwt[p];
            int4   ci = cit[p];
            float4 v0 = __ldg((const float4*)(xtc + ci.x + cg16));
            float4 v1 = __ldg((const float4*)(xtc + ci.y + cg16));
            float4 v2 = __ldg((const float4*)(xtc + ci.z + cg16));
            float4 v3 = __ldg((const float4*)(xtc + ci.w + cg16));
            float4 r;
            r.x = cw.x*v0.x + cw.y*v1.x + cw.z*v2.x + cw.w*v3.x;
            r.y = cw.x*v0.y + cw.y*v1.y + cw.z*v2.y + cw.w*v3.y;
            r.z = cw.x*v0.z + cw.y*v1.z + cw.z*v2.z + cw.w*v3.z;
            r.w = cw.x*v0.w + cw.y*v1.w + cw.z*v2.w + cw.w*v3.w;
            *(float4*)(smem + S_SAMP0 + p*ST + g_cg*4) = r;
        }
    }
    __syncthreads();

    float acc[2][4][4];
    #pragma unroll
    for (int t = 0; t < 2; t++)
        #pragma unroll
        for (int n = 0; n < 4; n++)
            #pragma unroll
            for (int e = 0; e < 4; e++) acc[t][n][e] = 0.f;

    #pragma unroll 1
    for (int k = 0; k < KT; k++) {
        const float* s_cur = smem + ((k & 1) ? S_SAMP1 : S_SAMP0);
        float*       s_nxt = smem + ((k & 1) ? S_SAMP0 : S_SAMP1);
        const bool pf = (k < KT-1);

        if (k < KT-2) calc_corners(k+2);   // writes buf[k&1]; gather below reads buf[(k+1)&1]

        const int nb = (k+1) & 1;
        const float4* cwt = (const float4*)(smem + S_CWB) + nb*64;
        const int4*   cit = (const int4*)(smem + S_CIB) + nb*64;

        const char* bq = (const char*)g_bf + ((size_t)(k*8)*8 + og*4)*256 + lane*8;
        uint2 bcur[4], bnxt[4];
        #pragma unroll
        for (int j = 0; j < 4; j++)
            bcur[j] = __ldg((const uint2*)(bq + j*256));
        bq += 2048;

        const int prow = pg*32 + (lane >> 2);

        #pragma unroll
        for (int q = 0; q < 8; q++) {
            // gather task q for tap k+1: issue corner LDG.128s (hidden by MMAs)
            float4 cw; int4 ci;
            float4 v0, v1, v2, v3;
            int gp = gpix0 + 2*q;
            if (pf) {
                cw = cwt[gp];
                ci = cit[gp];
                v0 = __ldg((const float4*)(xtc + ci.x + cg16));
                v1 = __ldg((const float4*)(xtc + ci.y + cg16));
                v2 = __ldg((const float4*)(xtc + ci.z + cg16));
                v3 = __ldg((const float4*)(xtc + ci.w + cg16));
            }
            if (q < 7) {
                #pragma unroll
                for (int j = 0; j < 4; j++)
                    bnxt[j] = __ldg((const uint2*)(bq + j*256));
                bq += 2048;
            }

            // A fragments from current samp, hi/lo derived in registers
            const int ccol = q*8 + (lane & 3);
            uint32_t ah[2][4], al[2][4];
            #pragma unroll
            for (int tt = 0; tt < 2; tt++) {
                const float* ps = s_cur + (prow + 16*tt)*ST + ccol;
                float a0 = ps[0];
                float a1 = ps[8*ST];
                float a2 = ps[4];
                float a3 = ps[8*ST + 4];
                float h0 = tf32r(a0), h1 = tf32r(a1), h2 = tf32r(a2), h3 = tf32r(a3);
                ah[tt][0] = __float_as_uint(h0);
                ah[tt][1] = __float_as_uint(h1);
                ah[tt][2] = __float_as_uint(h2);
                ah[tt][3] = __float_as_uint(h3);
                al[tt][0] = __float_as_uint(a0 - h0);
                al[tt][1] = __float_as_uint(a1 - h1);
                al[tt][2] = __float_as_uint(a2 - h2);
                al[tt][3] = __float_as_uint(a3 - h3);
            }
            #pragma unroll
            for (int j = 0; j < 4; j++) {
                uint32_t b0 = bcur[j].x, b1 = bcur[j].y;
                mma_tf32(acc[0][j], ah[0], b0, b1);
                mma_tf32(acc[0][j], al[0], b0, b1);
                mma_tf32(acc[1][j], ah[1], b0, b1);
                mma_tf32(acc[1][j], al[1], b0, b1);
            }
            #pragma unroll
            for (int j = 0; j < 4; j++) bcur[j] = bnxt[j];

            // combine and store gathered task
            if (pf) {
                float4 r;
                r.x = cw.x*v0.x + cw.y*v1.x + cw.z*v2.x + cw.w*v3.x;
                r.y = cw.x*v0.y + cw.y*v1.y + cw.z*v2.y + cw.w*v3.y;
                r.z = cw.x*v0.z + cw.y*v1.z + cw.z*v2.z + cw.w*v3.z;
                r.w = cw.x*v0.w + cw.y*v1.w + cw.z*v2.w + cw.w*v3.w;
                *(float4*)(s_nxt + gp*ST + g_cg*4) = r;
            }
        }

        __syncthreads();   // samp_nxt complete; corners(k+2) visible; samp_cur free
    }

    // ---- Epilogue: fragment regs -> out, add bias ----
    const int pix0 = pg*32 + (lane >> 2);
    const int o00  = og*32 + 2*(lane & 3);
    float* ob = out + (size_t)b*OO*HW + h*WW + w0;
    #pragma unroll
    for (int t = 0; t < 2; t++) {
        int p = pix0 + 16*t;
        #pragma unroll
        for (int j = 0; j < 4; j++) {
            int o = o00 + 8*j;
            float b0 = smem[S_BIAS + o];
            float b1 = smem[S_BIAS + o + 1];
            ob[(size_t)o*HW + p]         = acc[t][j][0] + b0;
            ob[(size_t)(o+1)*HW + p]     = acc[t][j][1] + b1;
            ob[(size_t)o*HW + p + 8]     = acc[t][j][2] + b0;
            ob[(size_t)(o+1)*HW + p + 8] = acc[t][j][3] + b1;
        }
    }
}

extern "C" void kernel_launch(void* const* d_in, const int* in_sizes, int n_in,
                              void* d_out, int out_size) {
    const float* x        = (const float*)d_in[0];
    const float* off_w    = (const float*)d_in[1];
    const float* off_b    = (const float*)d_in[2];
    const float* bn_gamma = (const float*)d_in[3];
    const float* bn_beta  = (const float*)d_in[4];
    const float* bn_mean  = (const float*)d_in[5];
    const float* bn_var   = (const float*)d_in[6];
    const float* dconv_w  = (const float*)d_in[7];
    const float* dconv_b  = (const float*)d_in[8];
    float* out = (float*)d_out;

    cudaFuncSetAttribute(deform_main_kernel,
                         cudaFuncAttributeMaxDynamicSharedMemorySize, SMEM_BYTES);

    prep_xt_kernel<<<BB*HH, 256>>>(x);
    prep_bf_kernel<<<(KT*8*8*32 + 255)/256, 256>>>(dconv_w);
    deform_main_kernel<<<BB*HH*2, 128, SMEM_BYTES>>>(
        x, off_w, off_b, bn_gamma, bn_beta, bn_mean, bn_var, dconv_b, out);
}

// round 13
// speedup vs baseline: 1.0818x; 1.0818x over previous
#include <cuda_runtime.h>
#include <math.h>
#include <stdint.h>

#define BB 4
#define CC 64
#define OO 64
#define HH 128
#define WW 128
#define HW (HH*WW)
#define KT 9
#define PX 64     // pixels per block (half row)
#define ST 68     // samp row stride (floats): 68 mod 32 == 4 -> conflict-free
#define CCB 256   // bytes per (y,x) position in x_t

// ---- smem layout (float offsets) ----
#define S_SAMP0 0                 // samp tf32 [64][68]   (4352)
#define S_SAMP1 4352              // samp tf32 [64][68]   (4352)
#define S_CWB   8704              // corner weights [2][64] float4  (512)
#define S_CIB   9216              // corner byte-offsets [2][64] int4 (512)
#define S_OFFJ  9728              // [18][64]             (1152)
#define S_OFFW  10880             // [64][20]             (1280)
#define S_SC    12160             // [18]
#define S_SB    12178             // [18]
#define S_BIAS  12196             // [64]
#define SMEM_FLOATS 12260
#define SMEM_BYTES (SMEM_FLOATS*4)

// transposed input: [B][H][W][C]
__device__ float g_xt[(size_t)BB*HH*WW*CC];
// B fragments (tf32): [k][q][nt][lane][2] = (b0, b1)
__device__ float g_bf[KT*8*8*32*2];

__device__ __forceinline__ float tf32r(float a) {
    uint32_t u;
    asm("cvt.rna.tf32.f32 %0, %1;" : "=r"(u) : "f"(a));
    return __uint_as_float(u);
}

// ---- transpose x [B][C][H][W] -> g_xt [B][H][W][C] ----
__global__ __launch_bounds__(256) void prep_xt_kernel(const float* __restrict__ x) {
    __shared__ float tile[64][129];
    const int blk = blockIdx.x;            // b*HH + h
    const int b = blk >> 7;
    const int h = blk & 127;
    const float* xs = x + (size_t)b*CC*HW + h*WW;
    const int tid = threadIdx.x;
    for (int idx = tid; idx < CC*WW; idx += 256) {
        int c = idx >> 7, w = idx & 127;
        tile[c][w] = xs[(size_t)c*HW + w];
    }
    __syncthreads();
    float4* ot = (float4*)(g_xt + (size_t)blk * WW * CC);
    for (int t = tid; t < WW*16; t += 256) {
        int cg = t & 15, w = t >> 4;
        ot[w*16 + cg] = make_float4(tile[4*cg][w], tile[4*cg+1][w],
                                    tile[4*cg+2][w], tile[4*cg+3][w]);
    }
}

__global__ void prep_bf_kernel(const float* __restrict__ w) {
    int i = blockIdx.x * 256 + threadIdx.x;         // over KT*8*8*32 = 18432
    if (i >= KT*8*8*32) return;
    int lane = i & 31;
    int nt   = (i >> 5) & 7;
    int q    = (i >> 8) & 7;
    int k    = i >> 11;
    int cc  = lane & 3;
    int gid = lane >> 2;
    int o   = nt*8 + gid;
    int c0  = q*8 + cc;
    int c1  = c0 + 4;
    float w0 = w[(o*CC + c0)*KT + k];
    float w1 = w[(o*CC + c1)*KT + k];
    ((float2*)g_bf)[i] = make_float2(tf32r(w0), tf32r(w1));
}

__device__ __forceinline__ void mma_tf32(float* d, const uint32_t* a, uint32_t b0, uint32_t b1) {
    asm volatile(
        "mma.sync.aligned.m16n8k8.row.col.f32.tf32.tf32.f32 "
        "{%0,%1,%2,%3}, {%4,%5,%6,%7}, {%8,%9}, {%0,%1,%2,%3};"
        : "+f"(d[0]), "+f"(d[1]), "+f"(d[2]), "+f"(d[3])
        : "r"(a[0]), "r"(a[1]), "r"(a[2]), "r"(a[3]), "r"(b0), "r"(b1));
}

__global__ __launch_bounds__(128, 4) void deform_main_kernel(
    const float* __restrict__ x,
    const float* __restrict__ off_w,
    const float* __restrict__ off_b,
    const float* __restrict__ bn_gamma,
    const float* __restrict__ bn_beta,
    const float* __restrict__ bn_mean,
    const float* __restrict__ bn_var,
    const float* __restrict__ dconv_b,
    float* __restrict__ out)
{
    extern __shared__ float smem[];

    const int tid  = threadIdx.x;
    const int lane = tid & 31;
    const int wid  = tid >> 5;          // 4 warps
    const int blk  = blockIdx.x;        // 1024 = BB*HH*2
    const int b    = blk >> 8;
    const int h    = (blk >> 1) & 127;
    const int w0   = (blk & 1) * PX;    // half-row pixel base
    const int pix  = tid & 63;          // pixel for offset branch
    const int half = tid >> 6;
    const float* xb = x + (size_t)b * CC * HW;
    const char* xtc = (const char*)g_xt + (size_t)b * HH * WW * CCB;

    // ---- Prologue ----
    for (int i = tid; i < 18*CC; i += 128) {
        int j = i / CC, c = i % CC;
        smem[S_OFFW + c*20 + j] = off_w[i];
    }
    if (tid < 18) {
        float sc = bn_gamma[tid] * rsqrtf(bn_var[tid] + 1e-5f);
        smem[S_SC + tid] = sc;
        smem[S_SB + tid] = (off_b[tid] - bn_mean[tid]) * sc + bn_beta[tid];
    }
    if (tid >= 64 && tid < 128) smem[S_BIAS + tid - 64] = dconv_b[tid - 64];
    __syncthreads();

    // ---- Offset branch: 2 threads per pixel, 9 j's each (original layout x) ----
    {
        const int jb = half * 9;
        const int p  = h*WW + w0 + pix;
        float a9[9];
        #pragma unroll
        for (int j = 0; j < 9; j++) a9[j] = 0.f;
        #pragma unroll 4
        for (int c = 0; c < CC; c++) {
            float xv = __ldg(xb + c*HW + p);
            const float* r = smem + S_OFFW + c*20 + jb;
            #pragma unroll
            for (int j = 0; j < 9; j++) a9[j] += xv * r[j];
        }
        #pragma unroll
        for (int jj = 0; jj < 9; jj++) {
            int j = jb + jj;
            float v = a9[jj] * smem[S_SC + j] + smem[S_SB + j];
            smem[S_OFFJ + j*PX + pix] = tanhf(v) * 0.75f;
        }
    }
    __syncthreads();

    // corner calc for tap k -> smem tables buf[k&1] (threads 0..63, one pixel each)
    auto calc_corners = [&](int k) {
        if (tid < 64) {
            const int p = tid;
            const int kyi = k / 3 - 1;
            const int kxi = k % 3 - 1;
            float py = (float)(h + kyi)      + smem[S_OFFJ + (2*k)*PX + p];
            float px = (float)(w0 + p + kxi) + smem[S_OFFJ + (2*k+1)*PX + p];
            float fy = floorf(py), fx = floorf(px);
            float wy = py - fy,    wx = px - fx;
            int y0 = (int)fy, x0 = (int)fx;
            int y1 = y0 + 1,  x1 = x0 + 1;
            float vy0 = (y0 >= 0 && y0 < HH) ? 1.f : 0.f;
            float vy1 = (y1 >= 0 && y1 < HH) ? 1.f : 0.f;
            float vx0 = (x0 >= 0 && x0 < WW) ? 1.f : 0.f;
            float vx1 = (x1 >= 0 && x1 < WW) ? 1.f : 0.f;
            float4 wv;
            wv.x = (1.f - wy) * (1.f - wx) * vy0 * vx0;
            wv.y = (1.f - wy) * wx         * vy0 * vx1;
            wv.z = wy         * (1.f - wx) * vy1 * vx0;
            wv.w = wy         * wx         * vy1 * vx1;
            int yc0 = min(max(y0, 0), HH-1), yc1 = min(max(y1, 0), HH-1);
            int xc0 = min(max(x0, 0), WW-1), xc1 = min(max(x1, 0), WW-1);
            int4 iv;
            iv.x = (yc0*WW + xc0)*CCB; iv.y = (yc0*WW + xc1)*CCB;
            iv.z = (yc1*WW + xc0)*CCB; iv.w = (yc1*WW + xc1)*CCB;
            ((float4*)(smem + S_CWB))[(k & 1)*64 + p] = wv;
            ((int4*)  (smem + S_CIB))[(k & 1)*64 + p] = iv;
        }
    };

    // gather roles: warp covers pixels [16*wid, 16*wid+16); lane = (pp, cg)
    const int g_pp  = lane >> 4;        // 0/1
    const int g_cg  = lane & 15;        // channel group (4 ch)
    const int cg16  = g_cg * 16;        // byte offset within position
    const int gpix0 = 16*wid + g_pp;

    // MMA warp roles
    const int pg = wid >> 1;
    const int og = wid & 1;

    // ---- Pre-loop: corners for taps 0,1; gather tap 0 -> SAMP0 (tf32-rounded) ----
    calc_corners(0);
    calc_corners(1);
    __syncthreads();
    {
        const float4* cwt = (const float4*)(smem + S_CWB);
        const int4*   cit = (const int4*)(smem + S_CIB);
        #pragma unroll
        for (int i = 0; i < 8; i++) {
            int p = gpix0 + 2*i;
            float4 cw = cwt[p];
            int4   ci = cit[p];
            float4 v0 = __ldg((const float4*)(xtc + ci.x + cg16));
            float4 v1 = __ldg((const float4*)(xtc + ci.y + cg16));
            float4 v2 = __ldg((const float4*)(xtc + ci.z + cg16));
            float4 v3 = __ldg((const float4*)(xtc + ci.w + cg16));
            float4 r;
            r.x = tf32r(cw.x*v0.x + cw.y*v1.x + cw.z*v2.x + cw.w*v3.x);
            r.y = tf32r(cw.x*v0.y + cw.y*v1.y + cw.z*v2.y + cw.w*v3.y);
            r.z = tf32r(cw.x*v0.z + cw.y*v1.z + cw.z*v2.z + cw.w*v3.z);
            r.w = tf32r(cw.x*v0.w + cw.y*v1.w + cw.z*v2.w + cw.w*v3.w);
            *(float4*)(smem + S_SAMP0 + p*ST + g_cg*4) = r;
        }
    }
    __syncthreads();

    float acc[2][4][4];
    #pragma unroll
    for (int t = 0; t < 2; t++)
        #pragma unroll
        for (int n = 0; n < 4; n++)
            #pragma unroll
            for (int e = 0; e < 4; e++) acc[t][n][e] = 0.f;

    #pragma unroll 1
    for (int k = 0; k < KT; k++) {
        const float* s_cur = smem + ((k & 1) ? S_SAMP1 : S_SAMP0);
        float*       s_nxt = smem + ((k & 1) ? S_SAMP0 : S_SAMP1);
        const bool pf = (k < KT-1);

        if (k < KT-2) calc_corners(k+2);   // writes buf[k&1]; gather reads buf[(k+1)&1]

        const int nb = (k+1) & 1;
        const float4* cwt = (const float4*)(smem + S_CWB) + nb*64;
        const int4*   cit = (const int4*)(smem + S_CIB) + nb*64;

        const char* bq = (const char*)g_bf + ((size_t)(k*8)*8 + og*4)*256 + lane*8;
        uint2 bcur[4], bnxt[4];
        #pragma unroll
        for (int j = 0; j < 4; j++)
            bcur[j] = __ldg((const uint2*)(bq + j*256));
        bq += 2048;

        const int prow = pg*32 + (lane >> 2);

        #pragma unroll
        for (int q = 0; q < 8; q++) {
            // gather task q for tap k+1: issue corner LDG.128s (hidden by MMAs)
            float4 cw; int4 ci;
            float4 v0, v1, v2, v3;
            int gp = gpix0 + 2*q;
            if (pf) {
                cw = cwt[gp];
                ci = cit[gp];
                v0 = __ldg((const float4*)(xtc + ci.x + cg16));
                v1 = __ldg((const float4*)(xtc + ci.y + cg16));
                v2 = __ldg((const float4*)(xtc + ci.z + cg16));
                v3 = __ldg((const float4*)(xtc + ci.w + cg16));
            }
            if (q < 7) {
                #pragma unroll
                for (int j = 0; j < 4; j++)
                    bnxt[j] = __ldg((const uint2*)(bq + j*256));
                bq += 2048;
            }

            // A fragments: samp already tf32 -> feed directly
            const int ccol = q*8 + (lane & 3);
            uint32_t af[2][4];
            #pragma unroll
            for (int tt = 0; tt < 2; tt++) {
                const float* ps = s_cur + (prow + 16*tt)*ST + ccol;
                af[tt][0] = __float_as_uint(ps[0]);
                af[tt][1] = __float_as_uint(ps[8*ST]);
                af[tt][2] = __float_as_uint(ps[4]);
                af[tt][3] = __float_as_uint(ps[8*ST + 4]);
            }
            #pragma unroll
            for (int j = 0; j < 4; j++) {
                mma_tf32(acc[0][j], af[0], bcur[j].x, bcur[j].y);
                mma_tf32(acc[1][j], af[1], bcur[j].x, bcur[j].y);
            }
            #pragma unroll
            for (int j = 0; j < 4; j++) bcur[j] = bnxt[j];

            // combine, round to tf32, store gathered task
            if (pf) {
                float4 r;
                r.x = tf32r(cw.x*v0.x + cw.y*v1.x + cw.z*v2.x + cw.w*v3.x);
                r.y = tf32r(cw.x*v0.y + cw.y*v1.y + cw.z*v2.y + cw.w*v3.y);
                r.z = tf32r(cw.x*v0.z + cw.y*v1.z + cw.z*v2.z + cw.w*v3.z);
                r.w = tf32r(cw.x*v0.w + cw.y*v1.w + cw.z*v2.w + cw.w*v3.w);
                *(float4*)(s_nxt + gp*ST + g_cg*4) = r;
            }
        }

        __syncthreads();   // samp_nxt complete; corners(k+2) visible; samp_cur free
    }

    // ---- Epilogue: fragment regs -> out, add bias ----
    const int pix0 = pg*32 + (lane >> 2);
    const int o00  = og*32 + 2*(lane & 3);
    float* ob = out + (size_t)b*OO*HW + h*WW + w0;
    #pragma unroll
    for (int t = 0; t < 2; t++) {
        int p = pix0 + 16*t;
        #pragma unroll
        for (int j = 0; j < 4; j++) {
            int o = o00 + 8*j;
            float b0 = smem[S_BIAS + o];
            float b1 = smem[S_BIAS + o + 1];
            ob[(size_t)o*HW + p]         = acc[t][j][0] + b0;
            ob[(size_t)(o+1)*HW + p]     = acc[t][j][1] + b1;
            ob[(size_t)o*HW + p + 8]     = acc[t][j][2] + b0;
            ob[(size_t)(o+1)*HW + p + 8] = acc[t][j][3] + b1;
        }
    }
}

extern "C" void kernel_launch(void* const* d_in, const int* in_sizes, int n_in,
                              void* d_out, int out_size) {
    const float* x        = (const float*)d_in[0];
    const float* off_w    = (const float*)d_in[1];
    const float* off_b    = (const float*)d_in[2];
    const float* bn_gamma = (const float*)d_in[3];
    const float* bn_beta  = (const float*)d_in[4];
    const float* bn_mean  = (const float*)d_in[5];
    const float* bn_var   = (const float*)d_in[6];
    const float* dconv_w  = (const float*)d_in[7];
    const float* dconv_b  = (const float*)d_in[8];
    float* out = (float*)d_out;

    cudaFuncSetAttribute(deform_main_kernel,
                         cudaFuncAttributeMaxDynamicSharedMemorySize, SMEM_BYTES);

    prep_xt_kernel<<<BB*HH, 256>>>(x);
    prep_bf_kernel<<<(KT*8*8*32 + 255)/256, 256>>>(dconv_w);
    deform_main_kernel<<<BB*HH*2, 128, SMEM_BYTES>>>(
        x, off_w, off_b, bn_gamma, bn_beta, bn_mean, bn_var, dconv_b, out);
}